// round 13
// baseline (speedup 1.0000x reference)
#include <cuda_runtime.h>
#include <cuda_fp16.h>
#include <math.h>

#define FDIM 128
#define NMAX 400000
#define BMAX 10000
#define APAD 136

// ---------------- scratch (device globals; no runtime alloc) ----------------
__device__ float g_kq[BMAX * FDIM];
__device__ float g_v [BMAX * FDIM];
__device__ float g_kb[BMAX];
__device__ float g_M [FDIM * 2];
__device__ float g_mb[2];
__device__ float g_p [NMAX];
__device__ float g_anorm[BMAX];
__device__ float g_Z;
// B fragments, per-lane mma layout: [3 stages][8 ksteps][16 ntiles][32 lanes]
__device__ uint2 g_Bf[3 * 8 * 16 * 32];

// ---------------- small helpers ---------------------------------------------
__device__ __forceinline__ float ssp(float x) {
    if (x > 15.f) return x - 0.69314718055994531f;
    return __logf(1.f + __expf(x)) - 0.69314718055994531f;
}
__device__ __forceinline__ unsigned smem_u32(const void* p) {
    unsigned a;
    asm("{ .reg .u64 t; cvta.to.shared.u64 t, %1; cvt.u32.u64 %0, t; }"
        : "=r"(a) : "l"(p));
    return a;
}
__device__ __forceinline__ unsigned pack_h2(float a, float b) {
    __half2 h = __halves2half2(__float2half_rn(a), __float2half_rn(b));
    return *(unsigned*)&h;
}

// mma.sync m16n8k16 row.col fp16 -> f32 accum (arch-generic, valid at sm_103)
#define MMA16816(c0, c1, c2, c3, a0, a1, a2, a3, b0, b1) \
    asm volatile("mma.sync.aligned.m16n8k16.row.col.f32.f16.f16.f32 " \
                 "{%0,%1,%2,%3},{%4,%5,%6,%7},{%8,%9},{%0,%1,%2,%3};" \
                 : "+f"(c0), "+f"(c1), "+f"(c2), "+f"(c3) \
                 : "r"(a0), "r"(a1), "r"(a2), "r"(a3), "r"(b0), "r"(b1))

#define LDMATRIX_X4(r0, r1, r2, r3, addr) \
    asm volatile("ldmatrix.sync.aligned.m8n8.x4.shared.b16 {%0,%1,%2,%3}, [%4];" \
                 : "=r"(r0), "=r"(r1), "=r"(r2), "=r"(r3) : "r"(addr))

// ---------------- K_setup: init accumulators + prep M/mb + weight conv ------
__global__ void k_setup(const float* __restrict__ Wq,
                        const float* __restrict__ bq,
                        const float* __restrict__ Wk,
                        const float* __restrict__ W1,
                        const float* __restrict__ W2,
                        const float* __restrict__ Wo, int B) {
    int blk = blockIdx.x, tid = threadIdx.x;
    if (blk < 48) {
        int i = blk * 256 + tid;                     // 12288 fragments
        int lane = i & 31, t = (i >> 5) & 15, ks = (i >> 9) & 7, s = i >> 12;
        const float* W = (s == 0) ? W1 : ((s == 1) ? W2 : Wo);
        int n  = t * 8 + (lane >> 2);
        int k0 = ks * 16 + (lane & 3) * 2;
        const float* row = W + n * FDIM;
        uint2 o;
        o.x = pack_h2(row[k0],     row[k0 + 1]);
        o.y = pack_h2(row[k0 + 8], row[k0 + 9]);
        g_Bf[i] = o;
    } else if (blk == 48) {
        int j = tid & (FDIM - 1);
        int c = tid >> 7;
        float s = 0.f;
        for (int f = 0; f < FDIM; f++) s += Wq[f * FDIM + j] * Wk[f * 2 + c];
        g_M[j * 2 + c] = s;
        if (tid < 2) {
            float sb = 0.f;
            for (int f = 0; f < FDIM; f++) sb += Wk[f * 2 + tid] * bq[f];
            g_mb[tid] = sb;
        }
    } else {
        int i = (blk - 49) * 256 + tid;
        if (i < B) g_anorm[i] = 0.f;
        if (i == 0) g_Z = 0.f;
    }
}

// ---------------- K2: per-molecule kq, v, kb --------------------------------
__global__ void k_mol(const float* __restrict__ ef,
                      const float* __restrict__ Wv, int B) {
    int i = blockIdx.x * blockDim.x + threadIdx.x;
    if (i >= B * FDIM) return;
    int m = i >> 7, f = i & (FDIM - 1);
    float e  = ef[m];
    float e0 = fmaxf(e, 0.f), e1 = fmaxf(-e, 0.f);
    float h0 = e0 / fmaxf(e0, 1.f), h1 = e1 / fmaxf(e1, 1.f);
    g_kq[i] = g_M[f * 2 + 0] * h0 + g_M[f * 2 + 1] * h1;
    g_v [i] = Wv [f * 2 + 0] * e0 + Wv [f * 2 + 1] * e1;
    if (f == 0) g_kb[m] = g_mb[0] * h0 + g_mb[1] * h1;
}

// ---------------- K3: logits -> p = exp(w) (no max pass), anorm, Z ----------
__global__ void k_w(const float* __restrict__ x,
                    const int* __restrict__ idx, int N) {
    int warp = (blockIdx.x * blockDim.x + threadIdx.x) >> 5;
    int lane = threadIdx.x & 31;
    int base = warp * 8;
    float pv = 0.f; int pm = -1;
    int mfirst = 0, mlast = 0;

    if (base < N) {
        float s[8];
        int   m[8];
        #pragma unroll
        for (int j = 0; j < 8; j++) {
            int n = base + j;
            s[j] = 0.f; m[j] = 0;
            if (n < N) {
                m[j] = idx[n];
                float4 a = ((const float4*)(x    + (size_t)n    * FDIM))[lane];
                float4 b = ((const float4*)(g_kq + (size_t)m[j] * FDIM))[lane];
                s[j] = a.x * b.x + a.y * b.y + a.z * b.z + a.w * b.w;
            }
        }
        #pragma unroll
        for (int j = 0; j < 8; j++) {
            #pragma unroll
            for (int o = 16; o; o >>= 1) s[j] += __shfl_xor_sync(~0u, s[j], o);
        }
        #pragma unroll
        for (int j = 0; j < 8; j++) {
            int n = base + j;
            if (lane == j && n < N) {
                pv = __expf((s[j] + g_kb[m[j]]) * 0.08838834764831844f);
                pm = m[j];
                g_p[n] = pv;
            }
        }
        mfirst = m[0];
        mlast  = m[(N - base >= 8) ? 7 : (N - 1 - base)];
    }

    if (base < N && mfirst == mlast) {
        float t = pv;
        #pragma unroll
        for (int o = 16; o; o >>= 1) t += __shfl_xor_sync(~0u, t, o);
        if (lane == 0) atomicAdd(&g_anorm[mfirst], t);
    } else if (pm >= 0) {
        atomicAdd(&g_anorm[pm], pv);
    }

    float z = pv;
    #pragma unroll
    for (int o = 16; o; o >>= 1) z += __shfl_xor_sync(~0u, z, o);
    __shared__ float red[8];
    if (lane == 0) red[threadIdx.x >> 5] = z;
    __syncthreads();
    if (threadIdx.x < 8) {
        float v = red[threadIdx.x];
        #pragma unroll
        for (int o = 4; o; o >>= 1) v += __shfl_xor_sync(0xffu, v, o);
        if (threadIdx.x == 0) atomicAdd(&g_Z, v);
    }
}

// ---------------- K5: fused residual MLP (fp16 HMMA, 4-way ILP chains) ------
// smem: sc[128] | smol[128] | A[128][APAD] fp16
#define OFF_SC  0
#define OFF_MOL 512
#define OFF_A   1024
#define SMEM_TOTAL (OFF_A + 128 * APAD * 2)

__device__ __forceinline__ void st_pair(char* sm, int r, int c, float a, float b) {
    *(unsigned*)(sm + OFF_A + (unsigned)(r * APAD + c) * 2u) = pack_h2(a, b);
}

__global__ void __launch_bounds__(256, 3)
k_mlp(const int* __restrict__ idx, float* __restrict__ out, int N) {
    extern __shared__ char sm[];
    float* sc   = (float*)(sm + OFF_SC);
    int*   smol = (int*)  (sm + OFF_MOL);
    int tid = threadIdx.x, wid = tid >> 5, lane = tid & 31;
    int n0 = blockIdx.x * 128;
    int r0 = wid * 16;

    if (tid < 128) {
        int n = n0 + tid; float c = 0.f; int m = 0;
        if (n < N) { m = idx[n]; c = g_p[n] / (g_anorm[m] + 1e-8f * g_Z); }
        sc[tid] = c; smol[tid] = m;
    }
    __syncthreads();

    // build stage-0 A tile: fp16(ssp(c * v))  (warp-local rows)
    {
        int r = tid >> 1, co = (tid & 1) * 64;
        float c = sc[r];
        const float4* vr = (const float4*)(g_v + (size_t)smol[r] * FDIM + co);
        #pragma unroll
        for (int q = 0; q < 16; q++) {
            float4 v = vr[q];
            int j = co + q * 4;
            st_pair(sm, r, j,     ssp(c * v.x), ssp(c * v.y));
            st_pair(sm, r, j + 2, ssp(c * v.z), ssp(c * v.w));
        }
    }
    __syncwarp();

    // ldmatrix source address for this lane (A frag m16k16, 4 8x8 tiles)
    int lrow = r0 + (lane & 7) + ((lane >> 3) & 1) * 8;
    int lkof = (lane >> 4) * 8;
    unsigned aA = smem_u32(sm + OFF_A) + (unsigned)(lrow * APAD + lkof) * 2u;

    int gr0 = r0 + (lane >> 2);        // epilogue rows
    int gr1 = gr0 + 8;
    int cofs = (lane & 3) * 2;         // epilogue col offset inside n-tile

    for (int s = 0; s < 3; s++) {
        // preload all A fragments for this stage (32 regs)
        unsigned af[8][4];
        #pragma unroll
        for (int ks = 0; ks < 8; ks++)
            LDMATRIX_X4(af[ks][0], af[ks][1], af[ks][2], af[ks][3],
                        aA + (unsigned)(ks * 32));

        const uint2* Bp = g_Bf + (s * 8) * 16 * 32 + lane;
        float ca = 0.f, cb = 0.f;
        const float* va = 0; const float* vb = 0;
        if (s == 1) {
            ca = sc[gr0]; cb = sc[gr1];
            va = g_v + (size_t)smol[gr0] * FDIM;
            vb = g_v + (size_t)smol[gr1] * FDIM;
        }

        // t-outer: 4 independent accumulator chains per iteration
        #pragma unroll
        for (int tp = 0; tp < 4; tp++) {
            float acc[4][4];
            #pragma unroll
            for (int q = 0; q < 4; q++) {
                acc[q][0] = 0.f; acc[q][1] = 0.f;
                acc[q][2] = 0.f; acc[q][3] = 0.f;
            }
            #pragma unroll
            for (int ks = 0; ks < 8; ks++) {
                #pragma unroll
                for (int q = 0; q < 4; q++) {
                    uint2 b = Bp[(ks * 16 + tp + q * 4) * 32];
                    MMA16816(acc[q][0], acc[q][1], acc[q][2], acc[q][3],
                             af[ks][0], af[ks][1], af[ks][2], af[ks][3],
                             b.x, b.y);
                }
            }
            #pragma unroll
            for (int q = 0; q < 4; q++) {
                int c = (tp + q * 4) * 8 + cofs;
                if (s == 2) {
                    int na = n0 + gr0, nb = n0 + gr1;
                    if (na < N)
                        *(float2*)(out + (size_t)na * FDIM + c) =
                            make_float2(acc[q][0], acc[q][1]);
                    if (nb < N)
                        *(float2*)(out + (size_t)nb * FDIM + c) =
                            make_float2(acc[q][2], acc[q][3]);
                } else if (s == 0) {
                    st_pair(sm, gr0, c, ssp(acc[q][0]), ssp(acc[q][1]));
                    st_pair(sm, gr1, c, ssp(acc[q][2]), ssp(acc[q][3]));
                } else {
                    float2 v0 = *(const float2*)(va + c);
                    float2 v1 = *(const float2*)(vb + c);
                    st_pair(sm, gr0, c, ssp(ca * v0.x + acc[q][0]),
                                        ssp(ca * v0.y + acc[q][1]));
                    st_pair(sm, gr1, c, ssp(cb * v1.x + acc[q][2]),
                                        ssp(cb * v1.y + acc[q][3]));
                }
            }
        }
        if (s < 2) __syncwarp();
    }
}

// ---------------- launcher --------------------------------------------------
extern "C" void kernel_launch(void* const* d_in, const int* in_sizes, int n_in,
                              void* d_out, int out_size) {
    const float* x  = (const float*)d_in[0];
    const float* ef = (const float*)d_in[1];
    const int*  idx = (const int*)  d_in[2];
    const float* Wq = (const float*)d_in[3];
    const float* bq = (const float*)d_in[4];
    const float* Wk = (const float*)d_in[5];
    const float* Wv = (const float*)d_in[6];
    const float* W1 = (const float*)d_in[7];
    const float* W2 = (const float*)d_in[8];
    const float* Wo = (const float*)d_in[9];
    float* out = (float*)d_out;

    int N = in_sizes[0] / FDIM;
    int B = in_sizes[1];

    cudaFuncSetAttribute(k_mlp, cudaFuncAttributeMaxDynamicSharedMemorySize,
                         SMEM_TOTAL);

    k_setup<<<49 + (B + 255) / 256, 256>>>(Wq, bq, Wk, W1, W2, Wo, B);
    k_mol<<<(B * FDIM + 255) / 256, 256>>>(ef, Wv, B);
    k_w<<<(N + 63) / 64, 256>>>(x, idx, N);
    k_mlp<<<(N + 127) / 128, 256, SMEM_TOTAL>>>(idx, out, N);
}